// round 10
// baseline (speedup 1.0000x reference)
#include <cuda_runtime.h>
#include <cuda_bf16.h>
#include <math.h>

// ---------------------------------------------------------------------------
// SMPL LBS point deformer — wide prep + heavy pass, overlapped via PDL.
// Inputs (metadata order):
//  0 points      (3, N)        float32
//  1 weights     (24, N)       float32
//  2 beta        (10,)         float32
//  3 theta       (24, 3)       float32
//  4 da_theta    (24, 3)       float32
//  5 shapedirs   (NV, 3, 10)   float32
//  6 v_template  (NV, 3)       float32
//  7 J_regressor (24, NV)      float32
// Output: (1, 3, N) float32
//
// Identity: J_pose = Jreg@v_template + (Jreg@shapedirs)@beta ; J_da = Jreg@v_template
// ---------------------------------------------------------------------------

#define NJ 24
#define NSPLIT 8          // v-dimension splits per joint -> grid = 24*8 = 192
#define NACC 33           // 3 template dots + 30 shapedir dots

__constant__ int c_par[NJ] = {-1,0,0,0,1,2,3,4,5,6,7,8,9,9,9,12,13,14,16,17,18,19,20,21};

__device__ float g_partial[NJ * NSPLIT * NACC];
__device__ float g_A[NJ * 12];     // row-major 3x4 per joint
__device__ int   g_ctr;            // zero-init; finisher resets each run

// ---------------------------------------------------------------------------
// Kernel 1: grid (NJ*NSPLIT) blocks, 256 threads.
// Block (j,s): partial sums of [Jreg@v_template | Jreg@shapedirs] over its
// v-range. Last-finishing block reduces, applies beta, Rodrigues, chain,
// pack, A = pose * rigid_inverse(da), then triggers dependent launch.
// ---------------------------------------------------------------------------
__global__ void __launch_bounds__(256) k_prep(
    const float* __restrict__ Jreg,
    const float* __restrict__ v_template,
    const float* __restrict__ shapedirs,
    const float* __restrict__ beta,
    const float* __restrict__ theta,
    const float* __restrict__ da_theta,
    int nv) {
    const int bx  = blockIdx.x;
    const int j   = bx / NSPLIT;
    const int sp  = bx % NSPLIT;
    const int tid = threadIdx.x;
    const int chunk = (nv + NSPLIT - 1) / NSPLIT;
    const int v0 = sp * chunk;
    const int v1 = min(nv, v0 + chunk);

    float acc[NACC];
#pragma unroll
    for (int k = 0; k < NACC; k++) acc[k] = 0.f;

    const float* r = Jreg + (size_t)j * nv;
    for (int v = v0 + tid; v < v1; v += 256) {
        float w = r[v];
        acc[0] += w * v_template[v * 3 + 0];
        acc[1] += w * v_template[v * 3 + 1];
        acc[2] += w * v_template[v * 3 + 2];
        const float* sd = shapedirs + (size_t)v * 30;
#pragma unroll
        for (int m = 0; m < 30; m++) acc[3 + m] += w * sd[m];
    }

    __shared__ float red[8][NACC];
    int lane = tid & 31, warp = tid >> 5;
#pragma unroll
    for (int k = 0; k < NACC; k++) {
        float v = acc[k];
#pragma unroll
        for (int off = 16; off > 0; off >>= 1)
            v += __shfl_down_sync(0xffffffffu, v, off);
        if (lane == 0) red[warp][k] = v;
    }
    __syncthreads();
    if (tid < NACC) {
        float s = 0.f;
#pragma unroll
        for (int w = 0; w < 8; w++) s += red[w][tid];
        g_partial[bx * NACC + tid] = s;
    }
    __syncthreads();

    __shared__ int s_last;
    if (tid == 0) {
        __threadfence();
        s_last = (atomicAdd(&g_ctr, 1) == NJ * NSPLIT - 1);
    }
    __syncthreads();
    if (!s_last) {
        // not the finisher: allow dependent launch progress from this block
        cudaTriggerProgrammaticLaunchCompletion();
        return;
    }
    __threadfence();

    // ---------------- finisher: reduce partials, build A ----------------
    __shared__ float sP[NJ][NACC];
    for (int i = tid; i < NJ * NACC; i += 256) {
        int jj = i / NACC, c = i % NACC;
        float s = 0.f;
#pragma unroll
        for (int sp2 = 0; sp2 < NSPLIT; sp2++)
            s += __ldcg(&g_partial[(jj * NSPLIT + sp2) * NACC + c]);
        sP[jj][c] = s;
    }
    __syncthreads();

    __shared__ float sJ[2][NJ * 3];    // [0]=pose, [1]=da
    if (tid < NJ) {
        int jj = tid;
        float b[10];
#pragma unroll
        for (int k = 0; k < 10; k++) b[k] = __ldg(&beta[k]);
#pragma unroll
        for (int c = 0; c < 3; c++) {
            float jd = sP[jj][c];
            float jp = jd;
#pragma unroll
            for (int k = 0; k < 10; k++) jp += sP[jj][3 + c * 10 + k] * b[k];
            sJ[0][jj * 3 + c] = jp;
            sJ[1][jj * 3 + c] = jd;
        }
    }
    __syncthreads();

    __shared__ float L[2][NJ][12];
    __shared__ float G[2][NJ][12];

    if (tid < 48) {
        int s = tid / NJ;          // 0 = pose, 1 = da
        int jj = tid % NJ;
        const float* th = (s == 0 ? theta : da_theta) + jj * 3;
        float rx = th[0], ry = th[1], rz = th[2];
        float nrm = sqrtf(rx * rx + ry * ry + rz * rz) + 1e-8f;
        float x = rx / nrm, y = ry / nrm, z = rz / nrm;
        float c = cosf(nrm), sn = sinf(nrm), ic = 1.0f - c;
        float* Lj = L[s][jj];
        Lj[0] = c + ic * x * x;      Lj[1] = ic * x * y - sn * z;  Lj[2] = ic * x * z + sn * y;
        Lj[3] = ic * x * y + sn * z; Lj[4] = c + ic * y * y;       Lj[5] = ic * y * z - sn * x;
        Lj[6] = ic * x * z - sn * y; Lj[7] = ic * y * z + sn * x;  Lj[8] = c + ic * z * z;
        const float* J = sJ[s];
        int p = c_par[jj];
        if (p < 0) {
            Lj[9] = J[0]; Lj[10] = J[1]; Lj[11] = J[2];
        } else {
            Lj[9]  = J[jj * 3 + 0] - J[p * 3 + 0];
            Lj[10] = J[jj * 3 + 1] - J[p * 3 + 1];
            Lj[11] = J[jj * 3 + 2] - J[p * 3 + 2];
        }
    }
    __syncthreads();

    if (tid < 2) {
        int s = tid;
        for (int k = 0; k < 12; k++) G[s][0][k] = L[s][0][k];
        for (int jj = 1; jj < NJ; jj++) {
            int p = c_par[jj];
            const float* Gp = G[s][p];
            const float* Lj = L[s][jj];
            float* Gj = G[s][jj];
            for (int rr = 0; rr < 3; rr++) {
                for (int cc = 0; cc < 3; cc++)
                    Gj[rr * 3 + cc] = Gp[rr * 3 + 0] * Lj[0 * 3 + cc] +
                                      Gp[rr * 3 + 1] * Lj[1 * 3 + cc] +
                                      Gp[rr * 3 + 2] * Lj[2 * 3 + cc];
                Gj[9 + rr] = Gp[rr * 3 + 0] * Lj[9] + Gp[rr * 3 + 1] * Lj[10] +
                             Gp[rr * 3 + 2] * Lj[11] + Gp[9 + rr];
            }
        }
        // pack: t -= R @ J_rest
        for (int jj = 0; jj < NJ; jj++) {
            const float* J = &sJ[s][jj * 3];
            float* Gj = G[s][jj];
            for (int rr = 0; rr < 3; rr++)
                Gj[9 + rr] -= Gj[rr * 3 + 0] * J[0] + Gj[rr * 3 + 1] * J[1] +
                              Gj[rr * 3 + 2] * J[2];
        }
    }
    __syncthreads();

    if (tid < NJ) {
        int jj = tid;
        const float* P = G[0][jj];   // pose
        const float* D = G[1][jj];   // da (rigid: R orthogonal)
        float AR[9];
        for (int rr = 0; rr < 3; rr++)
            for (int cc = 0; cc < 3; cc++)
                AR[rr * 3 + cc] = P[rr * 3 + 0] * D[cc * 3 + 0] +
                                  P[rr * 3 + 1] * D[cc * 3 + 1] +
                                  P[rr * 3 + 2] * D[cc * 3 + 2];
        float ti[3];
        for (int rr = 0; rr < 3; rr++)
            ti[rr] = -(D[0 * 3 + rr] * D[9] + D[1 * 3 + rr] * D[10] +
                       D[2 * 3 + rr] * D[11]);
        for (int rr = 0; rr < 3; rr++) {
            float at = P[rr * 3 + 0] * ti[0] + P[rr * 3 + 1] * ti[1] +
                       P[rr * 3 + 2] * ti[2] + P[9 + rr];
            g_A[jj * 12 + rr * 4 + 0] = AR[rr * 3 + 0];
            g_A[jj * 12 + rr * 4 + 1] = AR[rr * 3 + 1];
            g_A[jj * 12 + rr * 4 + 2] = AR[rr * 3 + 2];
            g_A[jj * 12 + rr * 4 + 3] = at;
        }
    }
    __syncthreads();
    if (tid == 0) {
        g_ctr = 0;          // reset for next replay (deterministic)
        __threadfence();    // publish g_A (+ reset) before releasing dependents
    }
    __syncthreads();
    cudaTriggerProgrammaticLaunchCompletion();
}

// ---------------------------------------------------------------------------
// Kernel 2: heavy per-point pass (measured 41.6us). Launched with PDL —
// issues its point loads concurrently with k_prep, then waits on the grid
// dependency only before reading g_A.
// ---------------------------------------------------------------------------
__device__ __forceinline__ unsigned long long fma2(unsigned long long a,
                                                   unsigned long long b,
                                                   unsigned long long c) {
    unsigned long long d;
    asm("fma.rn.f32x2 %0, %1, %2, %3;" : "=l"(d) : "l"(a), "l"(b), "l"(c));
    return d;
}

__device__ __forceinline__ ulonglong2 ldcs2(const ulonglong2* p) {
    ulonglong2 v;
    asm("ld.global.cs.v2.u64 {%0, %1}, [%2];"
        : "=l"(v.x), "=l"(v.y) : "l"(p));
    return v;
}

__device__ __forceinline__ void stcs2(ulonglong2* p, ulonglong2 v) {
    asm("st.global.cs.v2.u64 [%0], {%1, %2};" :: "l"(p), "l"(v.x), "l"(v.y)
        : "memory");
}

__global__ void __launch_bounds__(256, 4) k_lbs_vec(
    const float* __restrict__ points, const float* __restrict__ weights,
    float* __restrict__ out, int N, long long nGroups) {
    long long g = (long long)blockIdx.x * blockDim.x + threadIdx.x;
    bool act = (g < nGroups);
    long long gc = act ? g : 0;

    // Point loads do NOT depend on g_A — issue them before the grid sync so
    // they overlap with k_prep still running.
    ulonglong2 X, Y, Z;
    if (act) {
        X = ldcs2(reinterpret_cast<const ulonglong2*>(points) + gc);
        Y = ldcs2(reinterpret_cast<const ulonglong2*>(points + (size_t)N) + gc);
        Z = ldcs2(reinterpret_cast<const ulonglong2*>(points + 2 * (size_t)N) + gc);
    }

    // Wait for k_prep's trigger (g_A published).
    cudaGridDependencySynchronize();

    __shared__ __align__(16) unsigned long long sA[NJ * 12];  // {a,a} packed
    for (int i = threadIdx.x; i < NJ * 12; i += blockDim.x) {
        unsigned long long u = (unsigned long long)__float_as_uint(__ldcg(&g_A[i]));
        sA[i] = u | (u << 32);
    }
    __syncthreads();
    if (!act) return;

    unsigned long long vxa = 0ull, vya = 0ull, vza = 0ull;
    unsigned long long vxb = 0ull, vyb = 0ull, vzb = 0ull;

#pragma unroll
    for (int j = 0; j < NJ; j++) {
        const ulonglong2 W =
            ldcs2(reinterpret_cast<const ulonglong2*>(weights + (size_t)j * N) + g);
        const ulonglong2* ap = reinterpret_cast<const ulonglong2*>(&sA[j * 12]);
        const ulonglong2 a01 = ap[0], a23 = ap[1], a45 = ap[2];
        const ulonglong2 a67 = ap[3], a89 = ap[4], aAB = ap[5];
        unsigned long long s;
        // pair a (points 4g, 4g+1)
        s = fma2(a01.x, X.x, a23.y); s = fma2(a01.y, Y.x, s); s = fma2(a23.x, Z.x, s); vxa = fma2(W.x, s, vxa);
        s = fma2(a45.x, X.x, a67.y); s = fma2(a45.y, Y.x, s); s = fma2(a67.x, Z.x, s); vya = fma2(W.x, s, vya);
        s = fma2(a89.x, X.x, aAB.y); s = fma2(a89.y, Y.x, s); s = fma2(aAB.x, Z.x, s); vza = fma2(W.x, s, vza);
        // pair b (points 4g+2, 4g+3)
        s = fma2(a01.x, X.y, a23.y); s = fma2(a01.y, Y.y, s); s = fma2(a23.x, Z.y, s); vxb = fma2(W.y, s, vxb);
        s = fma2(a45.x, X.y, a67.y); s = fma2(a45.y, Y.y, s); s = fma2(a67.x, Z.y, s); vyb = fma2(W.y, s, vyb);
        s = fma2(a89.x, X.y, aAB.y); s = fma2(a89.y, Y.y, s); s = fma2(aAB.x, Z.y, s); vzb = fma2(W.y, s, vzb);
    }

    ulonglong2 o;
    o.x = vxa; o.y = vxb; stcs2(reinterpret_cast<ulonglong2*>(out) + g, o);
    o.x = vya; o.y = vyb; stcs2(reinterpret_cast<ulonglong2*>(out + (size_t)N) + g, o);
    o.x = vza; o.y = vzb; stcs2(reinterpret_cast<ulonglong2*>(out + 2 * (size_t)N) + g, o);
}

// Scalar fallback (only used if N % 4 != 0 — not the case for this problem).
__global__ void k_lbs_scalar(const float* __restrict__ points,
                             const float* __restrict__ weights,
                             float* __restrict__ out, int N) {
    __shared__ float sA[NJ * 12];
    for (int i = threadIdx.x; i < NJ * 12; i += blockDim.x) sA[i] = g_A[i];
    __syncthreads();
    long long n = (long long)blockIdx.x * blockDim.x + threadIdx.x;
    if (n >= N) return;
    float px = points[n], py = points[(size_t)N + n], pz = points[2 * (size_t)N + n];
    float vx = 0.f, vy = 0.f, vz = 0.f;
#pragma unroll
    for (int j = 0; j < NJ; j++) {
        float w = weights[(size_t)j * N + n];
        const float* a = &sA[j * 12];
        vx += w * (a[0] * px + a[1] * py + a[2]  * pz + a[3]);
        vy += w * (a[4] * px + a[5] * py + a[6]  * pz + a[7]);
        vz += w * (a[8] * px + a[9] * py + a[10] * pz + a[11]);
    }
    out[n] = vx; out[(size_t)N + n] = vy; out[2 * (size_t)N + n] = vz;
}

// ---------------------------------------------------------------------------
extern "C" void kernel_launch(void* const* d_in, const int* in_sizes, int n_in,
                              void* d_out, int out_size) {
    const float* points      = (const float*)d_in[0];
    const float* weights     = (const float*)d_in[1];
    const float* beta        = (const float*)d_in[2];
    const float* theta       = (const float*)d_in[3];
    const float* da_theta    = (const float*)d_in[4];
    const float* shapedirs   = (const float*)d_in[5];
    const float* v_template  = (const float*)d_in[6];
    const float* J_regressor = (const float*)d_in[7];

    int N  = in_sizes[0] / 3;          // number of points
    int NV = in_sizes[5] / 30;         // template vertex count

    // wide prep (grid 192 >= 148): partial joint sums + finisher transforms
    k_prep<<<NJ * NSPLIT, 256>>>(J_regressor, v_template, shapedirs, beta,
                                 theta, da_theta, NV);

    if ((N & 3) == 0) {
        long long nGroups = (long long)N / 4;
        int blocks = (int)((nGroups + 255) / 256);

        // PDL launch: overlap with k_prep, sync inside before reading g_A.
        cudaLaunchConfig_t cfg = {};
        cfg.gridDim  = dim3((unsigned)blocks, 1, 1);
        cfg.blockDim = dim3(256, 1, 1);
        cfg.dynamicSmemBytes = 0;
        cudaLaunchAttribute attrs[1];
        attrs[0].id = cudaLaunchAttributeProgrammaticStreamSerialization;
        attrs[0].val.programmaticStreamSerializationAllowed = 1;
        cfg.attrs = attrs;
        cfg.numAttrs = 1;
        cudaError_t err = cudaLaunchKernelEx(&cfg, k_lbs_vec,
                                             points, weights, (float*)d_out,
                                             N, nGroups);
        if (err != cudaSuccess) {
            // fallback: plain serialized launch
            k_lbs_vec<<<blocks, 256>>>(points, weights, (float*)d_out, N, nGroups);
        }
    } else {
        int blocks = (N + 255) / 256;
        k_lbs_scalar<<<blocks, 256>>>(points, weights, (float*)d_out, N);
    }
}

// round 11
// speedup vs baseline: 1.0269x; 1.0269x over previous
#include <cuda_runtime.h>
#include <cuda_bf16.h>
#include <math.h>

// ---------------------------------------------------------------------------
// SMPL LBS point deformer — wide prep (1 vertex/thread) + heavy pass.
// Inputs (metadata order):
//  0 points      (3, N)        float32
//  1 weights     (24, N)       float32
//  2 beta        (10,)         float32
//  3 theta       (24, 3)       float32
//  4 da_theta    (24, 3)       float32
//  5 shapedirs   (NV, 3, 10)   float32
//  6 v_template  (NV, 3)       float32
//  7 J_regressor (24, NV)      float32
// Output: (1, 3, N) float32
//
// Identities used:
//   J_pose = Jreg@v_template + (Jreg@shapedirs)@beta ; J_da = Jreg@v_template
//   sum_j w_j = 1  =>  v = A23*p + sum_{j<23} w_j (A_j - A23) * p
// ---------------------------------------------------------------------------

#define NJ 24
#define NSPLIT 32         // v-dimension splits per joint -> grid = 24*32 = 768
#define NACC 33           // 3 template dots + 30 shapedir dots

__constant__ int c_par[NJ] = {-1,0,0,0,1,2,3,4,5,6,7,8,9,9,9,12,13,14,16,17,18,19,20,21};

__device__ float g_partial[NJ * NSPLIT * NACC];
__device__ float g_A[NJ * 12];     // row-major 3x4 per joint
__device__ int   g_ctr;            // zero-init; finisher resets each run

// ---------------------------------------------------------------------------
// Kernel 1: grid (NJ*NSPLIT) blocks, 256 threads, ONE vertex per thread.
// Block (j,s): partial sums of [Jreg@v_template | Jreg@shapedirs] over its
// v-range. Last-finishing block reduces, applies beta, Rodrigues, chain,
// pack, A = pose * rigid_inverse(da), then triggers dependent launch.
// ---------------------------------------------------------------------------
__global__ void __launch_bounds__(256) k_prep(
    const float* __restrict__ Jreg,
    const float* __restrict__ v_template,
    const float* __restrict__ shapedirs,
    const float* __restrict__ beta,
    const float* __restrict__ theta,
    const float* __restrict__ da_theta,
    int nv) {
    const int bx  = blockIdx.x;
    const int j   = bx / NSPLIT;
    const int sp  = bx % NSPLIT;
    const int tid = threadIdx.x;
    const int chunk = (nv + NSPLIT - 1) / NSPLIT;   // <= 256 for SMPL sizes
    const int v0 = sp * chunk;
    const int v1 = min(nv, v0 + chunk);
    const int v  = v0 + tid;

    float acc[NACC];
#pragma unroll
    for (int k = 0; k < NACC; k++) acc[k] = 0.f;

    if (v < v1) {
        float w = Jreg[(size_t)j * nv + v];
        acc[0] = w * v_template[v * 3 + 0];
        acc[1] = w * v_template[v * 3 + 1];
        acc[2] = w * v_template[v * 3 + 2];
        const float* sd = shapedirs + (size_t)v * 30;
#pragma unroll
        for (int m = 0; m < 30; m++) acc[3 + m] = w * sd[m];
    }

    __shared__ float red[8][NACC];
    int lane = tid & 31, warp = tid >> 5;
#pragma unroll
    for (int k = 0; k < NACC; k++) {
        float x = acc[k];
#pragma unroll
        for (int off = 16; off > 0; off >>= 1)
            x += __shfl_down_sync(0xffffffffu, x, off);
        if (lane == 0) red[warp][k] = x;
    }
    __syncthreads();
    if (tid < NACC) {
        float s = 0.f;
#pragma unroll
        for (int w = 0; w < 8; w++) s += red[w][tid];
        g_partial[bx * NACC + tid] = s;
    }
    __syncthreads();

    __shared__ int s_last;
    if (tid == 0) {
        __threadfence();
        s_last = (atomicAdd(&g_ctr, 1) == NJ * NSPLIT - 1);
    }
    __syncthreads();
    if (!s_last) {
        cudaTriggerProgrammaticLaunchCompletion();
        return;
    }
    __threadfence();

    // ---------------- finisher: reduce partials, build A ----------------
    __shared__ float sP[NJ][NACC];
    for (int i = tid; i < NJ * NACC; i += 256) {
        int jj = i / NACC, c = i % NACC;
        float s = 0.f;
#pragma unroll
        for (int sp2 = 0; sp2 < NSPLIT; sp2++)
            s += __ldcg(&g_partial[(jj * NSPLIT + sp2) * NACC + c]);
        sP[jj][c] = s;
    }
    __syncthreads();

    __shared__ float sJ[2][NJ * 3];    // [0]=pose, [1]=da
    if (tid < NJ) {
        int jj = tid;
        float b[10];
#pragma unroll
        for (int k = 0; k < 10; k++) b[k] = __ldg(&beta[k]);
#pragma unroll
        for (int c = 0; c < 3; c++) {
            float jd = sP[jj][c];
            float jp = jd;
#pragma unroll
            for (int k = 0; k < 10; k++) jp += sP[jj][3 + c * 10 + k] * b[k];
            sJ[0][jj * 3 + c] = jp;
            sJ[1][jj * 3 + c] = jd;
        }
    }
    __syncthreads();

    __shared__ float L[2][NJ][12];
    __shared__ float G[2][NJ][12];

    if (tid < 48) {
        int s = tid / NJ;          // 0 = pose, 1 = da
        int jj = tid % NJ;
        const float* th = (s == 0 ? theta : da_theta) + jj * 3;
        float rx = th[0], ry = th[1], rz = th[2];
        float nrm = sqrtf(rx * rx + ry * ry + rz * rz) + 1e-8f;
        float x = rx / nrm, y = ry / nrm, z = rz / nrm;
        float c = cosf(nrm), sn = sinf(nrm), ic = 1.0f - c;
        float* Lj = L[s][jj];
        Lj[0] = c + ic * x * x;      Lj[1] = ic * x * y - sn * z;  Lj[2] = ic * x * z + sn * y;
        Lj[3] = ic * x * y + sn * z; Lj[4] = c + ic * y * y;       Lj[5] = ic * y * z - sn * x;
        Lj[6] = ic * x * z - sn * y; Lj[7] = ic * y * z + sn * x;  Lj[8] = c + ic * z * z;
        const float* J = sJ[s];
        int p = c_par[jj];
        if (p < 0) {
            Lj[9] = J[0]; Lj[10] = J[1]; Lj[11] = J[2];
        } else {
            Lj[9]  = J[jj * 3 + 0] - J[p * 3 + 0];
            Lj[10] = J[jj * 3 + 1] - J[p * 3 + 1];
            Lj[11] = J[jj * 3 + 2] - J[p * 3 + 2];
        }
    }
    __syncthreads();

    if (tid < 2) {
        int s = tid;
        for (int k = 0; k < 12; k++) G[s][0][k] = L[s][0][k];
        for (int jj = 1; jj < NJ; jj++) {
            int p = c_par[jj];
            const float* Gp = G[s][p];
            const float* Lj = L[s][jj];
            float* Gj = G[s][jj];
            for (int rr = 0; rr < 3; rr++) {
                for (int cc = 0; cc < 3; cc++)
                    Gj[rr * 3 + cc] = Gp[rr * 3 + 0] * Lj[0 * 3 + cc] +
                                      Gp[rr * 3 + 1] * Lj[1 * 3 + cc] +
                                      Gp[rr * 3 + 2] * Lj[2 * 3 + cc];
                Gj[9 + rr] = Gp[rr * 3 + 0] * Lj[9] + Gp[rr * 3 + 1] * Lj[10] +
                             Gp[rr * 3 + 2] * Lj[11] + Gp[9 + rr];
            }
        }
        // pack: t -= R @ J_rest
        for (int jj = 0; jj < NJ; jj++) {
            const float* J = &sJ[s][jj * 3];
            float* Gj = G[s][jj];
            for (int rr = 0; rr < 3; rr++)
                Gj[9 + rr] -= Gj[rr * 3 + 0] * J[0] + Gj[rr * 3 + 1] * J[1] +
                              Gj[rr * 3 + 2] * J[2];
        }
    }
    __syncthreads();

    if (tid < NJ) {
        int jj = tid;
        const float* P = G[0][jj];   // pose
        const float* D = G[1][jj];   // da (rigid: R orthogonal)
        float AR[9];
        for (int rr = 0; rr < 3; rr++)
            for (int cc = 0; cc < 3; cc++)
                AR[rr * 3 + cc] = P[rr * 3 + 0] * D[cc * 3 + 0] +
                                  P[rr * 3 + 1] * D[cc * 3 + 1] +
                                  P[rr * 3 + 2] * D[cc * 3 + 2];
        float ti[3];
        for (int rr = 0; rr < 3; rr++)
            ti[rr] = -(D[0 * 3 + rr] * D[9] + D[1 * 3 + rr] * D[10] +
                       D[2 * 3 + rr] * D[11]);
        for (int rr = 0; rr < 3; rr++) {
            float at = P[rr * 3 + 0] * ti[0] + P[rr * 3 + 1] * ti[1] +
                       P[rr * 3 + 2] * ti[2] + P[9 + rr];
            g_A[jj * 12 + rr * 4 + 0] = AR[rr * 3 + 0];
            g_A[jj * 12 + rr * 4 + 1] = AR[rr * 3 + 1];
            g_A[jj * 12 + rr * 4 + 2] = AR[rr * 3 + 2];
            g_A[jj * 12 + rr * 4 + 3] = at;
        }
    }
    __syncthreads();
    if (tid == 0) {
        g_ctr = 0;          // reset for next replay (deterministic)
        __threadfence();    // publish g_A before releasing dependents
    }
    __syncthreads();
    cudaTriggerProgrammaticLaunchCompletion();
}

// ---------------------------------------------------------------------------
// Kernel 2: heavy per-point pass. Uses sum(w)=1: only 23 weight rows read.
//   v = A23*p + sum_{j<23} w_j (A_j - A23) * p
// ---------------------------------------------------------------------------
__device__ __forceinline__ unsigned long long fma2(unsigned long long a,
                                                   unsigned long long b,
                                                   unsigned long long c) {
    unsigned long long d;
    asm("fma.rn.f32x2 %0, %1, %2, %3;" : "=l"(d) : "l"(a), "l"(b), "l"(c));
    return d;
}

__device__ __forceinline__ unsigned long long add2(unsigned long long a,
                                                   unsigned long long b) {
    unsigned long long d;
    asm("add.rn.f32x2 %0, %1, %2;" : "=l"(d) : "l"(a), "l"(b));
    return d;
}

__device__ __forceinline__ ulonglong2 ldcs2(const ulonglong2* p) {
    ulonglong2 v;
    asm("ld.global.cs.v2.u64 {%0, %1}, [%2];"
        : "=l"(v.x), "=l"(v.y) : "l"(p));
    return v;
}

__device__ __forceinline__ void stcs2(ulonglong2* p, ulonglong2 v) {
    asm("st.global.cs.v2.u64 [%0], {%1, %2};" :: "l"(p), "l"(v.x), "l"(v.y)
        : "memory");
}

__global__ void __launch_bounds__(256, 4) k_lbs_vec(
    const float* __restrict__ points, const float* __restrict__ weights,
    float* __restrict__ out, int N, long long nGroups) {
    long long g = (long long)blockIdx.x * blockDim.x + threadIdx.x;
    bool act = (g < nGroups);
    long long gc = act ? g : 0;

    // Point loads don't depend on g_A — issue before the grid sync.
    ulonglong2 X, Y, Z;
    if (act) {
        X = ldcs2(reinterpret_cast<const ulonglong2*>(points) + gc);
        Y = ldcs2(reinterpret_cast<const ulonglong2*>(points + (size_t)N) + gc);
        Z = ldcs2(reinterpret_cast<const ulonglong2*>(points + 2 * (size_t)N) + gc);
    }

    cudaGridDependencySynchronize();

    // sD[j][k] = {d,d} with d = A[j][k] - A[23][k]  (j<23); sA23[k] = {a,a}
    __shared__ __align__(16) unsigned long long sD[23 * 12];
    __shared__ __align__(16) unsigned long long sA23[12];
    for (int i = threadIdx.x; i < NJ * 12; i += blockDim.x) {
        int k = i - (i / 12) * 12;
        float a   = __ldcg(&g_A[i]);
        float a23 = __ldcg(&g_A[23 * 12 + k]);
        if (i < 23 * 12) {
            float d = a - a23;
            unsigned long long u = (unsigned long long)__float_as_uint(d);
            sD[i] = u | (u << 32);
        } else {
            unsigned long long u = (unsigned long long)__float_as_uint(a);
            sA23[k] = u | (u << 32);
        }
    }
    __syncthreads();
    if (!act) return;

    unsigned long long vxa = 0ull, vya = 0ull, vza = 0ull;
    unsigned long long vxb = 0ull, vyb = 0ull, vzb = 0ull;

#pragma unroll
    for (int j = 0; j < 23; j++) {
        const ulonglong2 W =
            ldcs2(reinterpret_cast<const ulonglong2*>(weights + (size_t)j * N) + g);
        const ulonglong2* ap = reinterpret_cast<const ulonglong2*>(&sD[j * 12]);
        const ulonglong2 a01 = ap[0], a23_ = ap[1], a45 = ap[2];
        const ulonglong2 a67 = ap[3], a89 = ap[4], aAB = ap[5];
        unsigned long long s;
        // pair a (points 4g, 4g+1)
        s = fma2(a01.x, X.x, a23_.y); s = fma2(a01.y, Y.x, s); s = fma2(a23_.x, Z.x, s); vxa = fma2(W.x, s, vxa);
        s = fma2(a45.x, X.x, a67.y);  s = fma2(a45.y, Y.x, s); s = fma2(a67.x,  Z.x, s); vya = fma2(W.x, s, vya);
        s = fma2(a89.x, X.x, aAB.y);  s = fma2(a89.y, Y.x, s); s = fma2(aAB.x,  Z.x, s); vza = fma2(W.x, s, vza);
        // pair b (points 4g+2, 4g+3)
        s = fma2(a01.x, X.y, a23_.y); s = fma2(a01.y, Y.y, s); s = fma2(a23_.x, Z.y, s); vxb = fma2(W.y, s, vxb);
        s = fma2(a45.x, X.y, a67.y);  s = fma2(a45.y, Y.y, s); s = fma2(a67.x,  Z.y, s); vyb = fma2(W.y, s, vyb);
        s = fma2(a89.x, X.y, aAB.y);  s = fma2(a89.y, Y.y, s); s = fma2(aAB.x,  Z.y, s); vzb = fma2(W.y, s, vzb);
    }

    // epilogue: + A23 * p
    {
        const ulonglong2* ap = reinterpret_cast<const ulonglong2*>(sA23);
        const ulonglong2 a01 = ap[0], a23_ = ap[1], a45 = ap[2];
        const ulonglong2 a67 = ap[3], a89 = ap[4], aAB = ap[5];
        unsigned long long s;
        s = fma2(a01.x, X.x, a23_.y); s = fma2(a01.y, Y.x, s); s = fma2(a23_.x, Z.x, s); vxa = add2(vxa, s);
        s = fma2(a45.x, X.x, a67.y);  s = fma2(a45.y, Y.x, s); s = fma2(a67.x,  Z.x, s); vya = add2(vya, s);
        s = fma2(a89.x, X.x, aAB.y);  s = fma2(a89.y, Y.x, s); s = fma2(aAB.x,  Z.x, s); vza = add2(vza, s);
        s = fma2(a01.x, X.y, a23_.y); s = fma2(a01.y, Y.y, s); s = fma2(a23_.x, Z.y, s); vxb = add2(vxb, s);
        s = fma2(a45.x, X.y, a67.y);  s = fma2(a45.y, Y.y, s); s = fma2(a67.x,  Z.y, s); vyb = add2(vyb, s);
        s = fma2(a89.x, X.y, aAB.y);  s = fma2(a89.y, Y.y, s); s = fma2(aAB.x,  Z.y, s); vzb = add2(vzb, s);
    }

    ulonglong2 o;
    o.x = vxa; o.y = vxb; stcs2(reinterpret_cast<ulonglong2*>(out) + g, o);
    o.x = vya; o.y = vyb; stcs2(reinterpret_cast<ulonglong2*>(out + (size_t)N) + g, o);
    o.x = vza; o.y = vzb; stcs2(reinterpret_cast<ulonglong2*>(out + 2 * (size_t)N) + g, o);
}

// Scalar fallback (only used if N % 4 != 0 — not the case for this problem).
__global__ void k_lbs_scalar(const float* __restrict__ points,
                             const float* __restrict__ weights,
                             float* __restrict__ out, int N) {
    __shared__ float sA[NJ * 12];
    for (int i = threadIdx.x; i < NJ * 12; i += blockDim.x) sA[i] = g_A[i];
    __syncthreads();
    long long n = (long long)blockIdx.x * blockDim.x + threadIdx.x;
    if (n >= N) return;
    float px = points[n], py = points[(size_t)N + n], pz = points[2 * (size_t)N + n];
    float vx = 0.f, vy = 0.f, vz = 0.f;
#pragma unroll
    for (int j = 0; j < NJ; j++) {
        float w = weights[(size_t)j * N + n];
        const float* a = &sA[j * 12];
        vx += w * (a[0] * px + a[1] * py + a[2]  * pz + a[3]);
        vy += w * (a[4] * px + a[5] * py + a[6]  * pz + a[7]);
        vz += w * (a[8] * px + a[9] * py + a[10] * pz + a[11]);
    }
    out[n] = vx; out[(size_t)N + n] = vy; out[2 * (size_t)N + n] = vz;
}

// ---------------------------------------------------------------------------
extern "C" void kernel_launch(void* const* d_in, const int* in_sizes, int n_in,
                              void* d_out, int out_size) {
    const float* points      = (const float*)d_in[0];
    const float* weights     = (const float*)d_in[1];
    const float* beta        = (const float*)d_in[2];
    const float* theta       = (const float*)d_in[3];
    const float* da_theta    = (const float*)d_in[4];
    const float* shapedirs   = (const float*)d_in[5];
    const float* v_template  = (const float*)d_in[6];
    const float* J_regressor = (const float*)d_in[7];

    int N  = in_sizes[0] / 3;          // number of points
    int NV = in_sizes[5] / 30;         // template vertex count

    // wide prep (grid 768, 1 vertex/thread): partials + finisher transforms
    k_prep<<<NJ * NSPLIT, 256>>>(J_regressor, v_template, shapedirs, beta,
                                 theta, da_theta, NV);

    if ((N & 3) == 0) {
        long long nGroups = (long long)N / 4;
        int blocks = (int)((nGroups + 255) / 256);

        cudaLaunchConfig_t cfg = {};
        cfg.gridDim  = dim3((unsigned)blocks, 1, 1);
        cfg.blockDim = dim3(256, 1, 1);
        cfg.dynamicSmemBytes = 0;
        cudaLaunchAttribute attrs[1];
        attrs[0].id = cudaLaunchAttributeProgrammaticStreamSerialization;
        attrs[0].val.programmaticStreamSerializationAllowed = 1;
        cfg.attrs = attrs;
        cfg.numAttrs = 1;
        cudaError_t err = cudaLaunchKernelEx(&cfg, k_lbs_vec,
                                             points, weights, (float*)d_out,
                                             N, nGroups);
        if (err != cudaSuccess) {
            k_lbs_vec<<<blocks, 256>>>(points, weights, (float*)d_out, N, nGroups);
        }
    } else {
        int blocks = (N + 255) / 256;
        k_lbs_scalar<<<blocks, 256>>>(points, weights, (float*)d_out, N);
    }
}